// round 4
// baseline (speedup 1.0000x reference)
#include <cuda_runtime.h>
#include <math.h>

#define DIM     512
#define NBLK    256          // k1 grid size; <= 2 blocks/SM on 148 SMs (one wave + partial)
#define THREADS_X 128        // float4 lanes covering DIM
#define THREADS_Y 4

// Per-(block, dim) partial sums: {P = sum z, Q = sum z^2}. 256*512*8B = 1 MB.
__device__ float2 g_scratch[NBLK * DIM];

// ---------------------------------------------------------------------------
// Kernel 1: column-wise reduction of z [T, 512] -> per-block partial (P, Q)
// Fully coalesced float4 streaming; unroll-8 for MLP; smem y-reduction.
// ---------------------------------------------------------------------------
__global__ void __launch_bounds__(THREADS_X * THREADS_Y)
k1_reduce(const float* __restrict__ z, int rows_per_blk) {
    const int x = threadIdx.x;        // 0..127 : float4 lane -> dims 4x..4x+3
    const int y = threadIdx.y;        // 0..3   : row interleave
    const int b = blockIdx.x;

    const float4* __restrict__ zp = reinterpret_cast<const float4*>(z);

    float4 P = make_float4(0.f, 0.f, 0.f, 0.f);
    float4 Q = make_float4(0.f, 0.f, 0.f, 0.f);

    const long long row0 = (long long)b * rows_per_blk + y;
    const int iters = rows_per_blk / THREADS_Y;   // 64 for T=65536

    #pragma unroll 8
    for (int i = 0; i < iters; ++i) {
        float4 v = zp[(row0 + (long long)i * THREADS_Y) * (DIM / 4) + x];
        P.x += v.x; P.y += v.y; P.z += v.z; P.w += v.w;
        Q.x = fmaf(v.x, v.x, Q.x);
        Q.y = fmaf(v.y, v.y, Q.y);
        Q.z = fmaf(v.z, v.z, Q.z);
        Q.w = fmaf(v.w, v.w, Q.w);
    }

    __shared__ float4 sP[THREADS_Y][THREADS_X];
    __shared__ float4 sQ[THREADS_Y][THREADS_X];
    sP[y][x] = P;
    sQ[y][x] = Q;
    __syncthreads();

    if (y == 0) {
        float4 p = sP[0][x];
        float4 q = sQ[0][x];
        #pragma unroll
        for (int j = 1; j < THREADS_Y; ++j) {
            float4 pj = sP[j][x];
            float4 qj = sQ[j][x];
            p.x += pj.x; p.y += pj.y; p.z += pj.z; p.w += pj.w;
            q.x += qj.x; q.y += qj.y; q.z += qj.z; q.w += qj.w;
        }
        const int d0 = x * 4;
        float2* __restrict__ outp = &g_scratch[b * DIM + d0];
        outp[0] = make_float2(p.x, q.x);
        outp[1] = make_float2(p.y, q.y);
        outp[2] = make_float2(p.z, q.z);
        outp[3] = make_float2(p.w, q.w);
    }
}

// ---------------------------------------------------------------------------
// Kernel 2: reduce partials per dim, closed-form epilogue, scalar output.
//
// Per dimension d (s = pv - pc, w_t = s + pc*t):
//   sum_t log(2*pi*var_t) = T*log(2pi) + (T-1)*log(s) + log(s + T*pc)
//   sum_t (z_t - mu_t)^2 / var_t = (Q - pc/(s+T*pc) * P^2) / s
// with P = sum(z - mu0), Q = sum((z - mu0)^2),
// adjusted from raw sums: P = Sz - T*mu0, Q = Szz - 2*mu0*Sz + T*mu0^2.
// lkd_d = -0.5 * [ logdet-term + quad-term ]
// ---------------------------------------------------------------------------
__global__ void __launch_bounds__(DIM)
k2_final(const float* __restrict__ var_vbl,
         const float* __restrict__ corr_vbl,
         const float* __restrict__ prior_mu,
         float* __restrict__ out,
         int T) {
    const int d = threadIdx.x;

    const float2* __restrict__ sc = g_scratch;
    double Sz = 0.0, Szz = 0.0;
    #pragma unroll 16
    for (int b = 0; b < NBLK; ++b) {
        float2 pq = sc[b * DIM + d];
        Sz  += (double)pq.x;
        Szz += (double)pq.y;
    }

    const double Tn  = (double)T;
    const double x1  = (double)var_vbl[d];
    const double x2  = (double)corr_vbl[d];
    const double mu0 = (double)prior_mu[d];

    // softplus / sigmoid in double (cheap: runs once over 512 threads)
    const double sp = (x1 > 30.0) ? x1 : log1p(exp(x1));
    const double pv = sp * sp;
    const double sg = 1.0 / (1.0 + exp(-x2));
    const double pc = sg * pv;
    const double s  = pv - pc;

    const double P = Sz - Tn * mu0;
    const double Q = Szz - 2.0 * mu0 * Sz + Tn * mu0 * mu0;

    const double denom = s + Tn * pc;
    const double quad  = (Q - (pc / denom) * P * P) / s;

    const double LOG_2PI = 1.8378770664093454835606594728112; // log(2*pi)
    const double lkd_d = -0.5 * (Tn * LOG_2PI + (Tn - 1.0) * log(s)
                                 + log(denom) + quad);

    __shared__ double red[DIM];
    red[d] = lkd_d;
    __syncthreads();
    #pragma unroll
    for (int off = DIM / 2; off > 0; off >>= 1) {
        if (d < off) red[d] += red[d + off];
        __syncthreads();
    }
    if (d == 0) out[0] = (float)red[0];
}

// ---------------------------------------------------------------------------
extern "C" void kernel_launch(void* const* d_in, const int* in_sizes, int n_in,
                              void* d_out, int out_size) {
    const float* z_rest   = (const float*)d_in[0];   // [T, 512]
    const float* var_vbl  = (const float*)d_in[1];   // [512]
    const float* corr_vbl = (const float*)d_in[2];   // [512]
    const float* prior_mu = (const float*)d_in[3];   // [512]
    float* out = (float*)d_out;

    const int T = in_sizes[0] / DIM;                 // 65536
    const int rows_per_blk = T / NBLK;               // 256

    dim3 blk1(THREADS_X, THREADS_Y);
    k1_reduce<<<NBLK, blk1>>>(z_rest, rows_per_blk);
    k2_final<<<1, DIM>>>(var_vbl, corr_vbl, prior_mu, out, T);
}

// round 5
// speedup vs baseline: 8.3153x; 8.3153x over previous
#include <cuda_runtime.h>
#include <math.h>

#define DIM     512
#define NBLK    256          // k1 grid size
#define THREADS_X 128        // float4 lanes covering DIM
#define THREADS_Y 4

// Per-(block, dim) partial sums: {P = sum z, Q = sum z^2}. 256*512*8B = 1 MB.
__device__ float2 g_scratch[NBLK * DIM];

// ---------------------------------------------------------------------------
// Kernel 1: column-wise reduction of z [T, 512] -> per-block partial (P, Q)
// Fully coalesced float4 streaming; unroll-8 for MLP; smem y-reduction.
// ---------------------------------------------------------------------------
__global__ void __launch_bounds__(THREADS_X * THREADS_Y)
k1_reduce(const float* __restrict__ z, int rows_per_blk) {
    const int x = threadIdx.x;        // 0..127 : float4 lane -> dims 4x..4x+3
    const int y = threadIdx.y;        // 0..3   : row interleave
    const int b = blockIdx.x;

    const float4* __restrict__ zp = reinterpret_cast<const float4*>(z);

    float4 P = make_float4(0.f, 0.f, 0.f, 0.f);
    float4 Q = make_float4(0.f, 0.f, 0.f, 0.f);

    const long long row0 = (long long)b * rows_per_blk + y;
    const int iters = rows_per_blk / THREADS_Y;   // 64 for T=65536

    #pragma unroll 8
    for (int i = 0; i < iters; ++i) {
        float4 v = zp[(row0 + (long long)i * THREADS_Y) * (DIM / 4) + x];
        P.x += v.x; P.y += v.y; P.z += v.z; P.w += v.w;
        Q.x = fmaf(v.x, v.x, Q.x);
        Q.y = fmaf(v.y, v.y, Q.y);
        Q.z = fmaf(v.z, v.z, Q.z);
        Q.w = fmaf(v.w, v.w, Q.w);
    }

    __shared__ float4 sP[THREADS_Y][THREADS_X];
    __shared__ float4 sQ[THREADS_Y][THREADS_X];
    sP[y][x] = P;
    sQ[y][x] = Q;
    __syncthreads();

    if (y == 0) {
        float4 p = sP[0][x];
        float4 q = sQ[0][x];
        #pragma unroll
        for (int j = 1; j < THREADS_Y; ++j) {
            float4 pj = sP[j][x];
            float4 qj = sQ[j][x];
            p.x += pj.x; p.y += pj.y; p.z += pj.z; p.w += pj.w;
            q.x += qj.x; q.y += qj.y; q.z += qj.z; q.w += qj.w;
        }
        const int d0 = x * 4;
        float2* __restrict__ outp = &g_scratch[b * DIM + d0];
        outp[0] = make_float2(p.x, q.x);
        outp[1] = make_float2(p.y, q.y);
        outp[2] = make_float2(p.z, q.z);
        outp[3] = make_float2(p.w, q.w);
    }
}

// ---------------------------------------------------------------------------
// Kernel 2 (ALL FP32 — no FP64 pipe): reduce partials per dim, closed-form
// epilogue, scalar output.
//
// Per dimension d (s = pv - pc):
//   sum_t log(2*pi*var_t) = T*log(2pi) + (T-1)*log(s) + log(s + T*pc)
//   sum_t (z_t - mu_t)^2 / var_t = (Q - pc/(s+T*pc) * P^2) / s
// with P = Sz - T*mu0, Q = Szz - 2*mu0*Sz + T*mu0^2.
// c0 = -0.5 * T * log(2pi) precomputed on host in double.
// ---------------------------------------------------------------------------
__global__ void __launch_bounds__(1024)
k2_final(const float* __restrict__ var_vbl,
         const float* __restrict__ corr_vbl,
         const float* __restrict__ prior_mu,
         float* __restrict__ out,
         int T, float c0) {
    const int t = threadIdx.x;       // 0..1023
    const int d = t & (DIM - 1);     // dim
    const int h = t >> 9;            // half: 0 or 1

    // Each thread sums 128 partials (coalesced: consecutive d -> consecutive
    // float2 in a row of g_scratch; L2-resident).
    const float2* __restrict__ sc = g_scratch;
    float Sz = 0.f, Szz = 0.f;
    const int half = NBLK / 2;       // 128
    #pragma unroll 8
    for (int i = 0; i < half; ++i) {
        float2 pq = sc[(h * half + i) * DIM + d];
        Sz  += pq.x;
        Szz += pq.y;
    }

    __shared__ float sSz[1024];
    __shared__ float sSzz[1024];
    __shared__ float red[DIM];
    sSz[t]  = Sz;
    sSzz[t] = Szz;
    __syncthreads();

    if (h == 0) {
        Sz  += sSz[t + DIM];
        Szz += sSzz[t + DIM];

        const float Tn  = (float)T;
        const float x1  = var_vbl[d];
        const float x2  = corr_vbl[d];
        const float mu0 = prior_mu[d];

        // softplus / sigmoid in fp32
        const float sp = (x1 > 20.0f) ? x1 : log1pf(expf(x1));
        const float pv = sp * sp;
        const float sg = 1.0f / (1.0f + expf(-x2));
        const float pc = sg * pv;
        const float s  = pv - pc;

        const float P = Sz - Tn * mu0;
        const float Q = Szz - 2.0f * mu0 * Sz + Tn * mu0 * mu0;

        const float denom = s + Tn * pc;
        const float quad  = (Q - (pc / denom) * P * P) / s;

        // lkd_d = c0 - 0.5*((T-1)*log s + log denom + quad)
        red[d] = c0 - 0.5f * ((Tn - 1.0f) * logf(s) + logf(denom) + quad);
    }
    __syncthreads();

    #pragma unroll
    for (int off = DIM / 2; off > 0; off >>= 1) {
        if (t < off) red[t] += red[t + off];
        __syncthreads();
    }
    if (t == 0) out[0] = red[0];
}

// ---------------------------------------------------------------------------
extern "C" void kernel_launch(void* const* d_in, const int* in_sizes, int n_in,
                              void* d_out, int out_size) {
    const float* z_rest   = (const float*)d_in[0];   // [T, 512]
    const float* var_vbl  = (const float*)d_in[1];   // [512]
    const float* corr_vbl = (const float*)d_in[2];   // [512]
    const float* prior_mu = (const float*)d_in[3];   // [512]
    float* out = (float*)d_out;

    const int T = in_sizes[0] / DIM;                 // 65536
    const int rows_per_blk = T / NBLK;               // 256

    // Big constant term computed once in host double precision.
    const double LOG_2PI = 1.8378770664093454835606594728112;
    const float c0 = (float)(-0.5 * (double)T * LOG_2PI);

    dim3 blk1(THREADS_X, THREADS_Y);
    k1_reduce<<<NBLK, blk1>>>(z_rest, rows_per_blk);
    k2_final<<<1, 1024>>>(var_vbl, corr_vbl, prior_mu, out, T, c0);
}

// round 6
// speedup vs baseline: 9.2445x; 1.1117x over previous
#include <cuda_runtime.h>
#include <math.h>

#define DIM     512
#define NBLK    512          // k1 grid size (2 MB scratch)
#define THREADS_X 128        // float4 lanes covering DIM
#define THREADS_Y 4
#define NB2A    16           // k2a grid size

// Level-1 partials: per (k1-block, dim-pair) float4 {P0,Q0,P1,Q1}.
// NBLK * (DIM/2) * 16B = 2 MB.
__device__ float4 g_scratch[NBLK * (DIM / 2)];
// Level-2 partials: NB2A * (DIM/2) * 16B = 64 KB.
__device__ float4 g_scratch2[NB2A * (DIM / 2)];

// ---------------------------------------------------------------------------
// Kernel 1: column-wise reduction of z [T, 512] -> per-block partial (P, Q)
// Fully coalesced float4 streaming; unroll-8 for MLP; smem y-reduction.
// ---------------------------------------------------------------------------
__global__ void __launch_bounds__(THREADS_X * THREADS_Y)
k1_reduce(const float* __restrict__ z, int rows_per_blk) {
    const int x = threadIdx.x;        // 0..127 : float4 lane -> dims 4x..4x+3
    const int y = threadIdx.y;        // 0..3   : row interleave
    const int b = blockIdx.x;

    const float4* __restrict__ zp = reinterpret_cast<const float4*>(z);

    float4 P = make_float4(0.f, 0.f, 0.f, 0.f);
    float4 Q = make_float4(0.f, 0.f, 0.f, 0.f);

    const long long row0 = (long long)b * rows_per_blk + y;
    const int iters = rows_per_blk / THREADS_Y;   // 32 for T=65536, NBLK=512

    #pragma unroll 8
    for (int i = 0; i < iters; ++i) {
        float4 v = zp[(row0 + (long long)i * THREADS_Y) * (DIM / 4) + x];
        P.x += v.x; P.y += v.y; P.z += v.z; P.w += v.w;
        Q.x = fmaf(v.x, v.x, Q.x);
        Q.y = fmaf(v.y, v.y, Q.y);
        Q.z = fmaf(v.z, v.z, Q.z);
        Q.w = fmaf(v.w, v.w, Q.w);
    }

    __shared__ float4 sP[THREADS_Y][THREADS_X];
    __shared__ float4 sQ[THREADS_Y][THREADS_X];
    sP[y][x] = P;
    sQ[y][x] = Q;
    __syncthreads();

    if (y == 0) {
        float4 p = sP[0][x];
        float4 q = sQ[0][x];
        #pragma unroll
        for (int j = 1; j < THREADS_Y; ++j) {
            float4 pj = sP[j][x];
            float4 qj = sQ[j][x];
            p.x += pj.x; p.y += pj.y; p.z += pj.z; p.w += pj.w;
            q.x += qj.x; q.y += qj.y; q.z += qj.z; q.w += qj.w;
        }
        // dim-pair layout: pair index pc = 2x (dims 4x,4x+1) and 2x+1 (4x+2,4x+3)
        float4* __restrict__ outp = &g_scratch[b * (DIM / 2) + 2 * x];
        outp[0] = make_float4(p.x, q.x, p.y, q.y);
        outp[1] = make_float4(p.z, q.z, p.w, q.w);
    }
}

// ---------------------------------------------------------------------------
// Kernel 2a: reduce NBLK partial rows -> NB2A partial rows, in parallel
// across NB2A SMs. Each block reduces NBLK/NB2A rows over all dim-pairs.
// ---------------------------------------------------------------------------
__global__ void __launch_bounds__(DIM / 2)
k2a_reduce() {
    const int j = threadIdx.x;            // dim-pair 0..255
    const int g = blockIdx.x;             // 0..NB2A-1
    const int rows = NBLK / NB2A;         // 32

    const float4* __restrict__ sc = g_scratch;
    float4 acc = make_float4(0.f, 0.f, 0.f, 0.f);
    #pragma unroll 8
    for (int r = 0; r < rows; ++r) {
        float4 v = sc[(g * rows + r) * (DIM / 2) + j];
        acc.x += v.x; acc.y += v.y; acc.z += v.z; acc.w += v.w;
    }
    g_scratch2[g * (DIM / 2) + j] = acc;
}

// ---------------------------------------------------------------------------
// Kernel 2b (ALL FP32): final reduce of NB2A rows + closed-form epilogue.
//
// Per dimension d (s = pv - pc):
//   sum_t log(2*pi*var_t) = T*log(2pi) + (T-1)*log(s) + log(s + T*pc)
//   sum_t (z_t - mu_t)^2 / var_t = (Q - pc/(s+T*pc) * P^2) / s
// with P = Sz - T*mu0, Q = Szz - 2*mu0*Sz + T*mu0^2.
// c0 = -0.5 * T * log(2pi) precomputed on host in double.
// ---------------------------------------------------------------------------
__global__ void __launch_bounds__(DIM / 2)
k2b_final(const float* __restrict__ var_vbl,
          const float* __restrict__ corr_vbl,
          const float* __restrict__ prior_mu,
          float* __restrict__ out,
          int T, float c0) {
    const int j = threadIdx.x;            // dim-pair 0..255 -> dims 2j, 2j+1

    const float4* __restrict__ sc = g_scratch2;
    float4 acc = make_float4(0.f, 0.f, 0.f, 0.f);
    #pragma unroll
    for (int g = 0; g < NB2A; ++g) {
        float4 v = sc[g * (DIM / 2) + j];
        acc.x += v.x; acc.y += v.y; acc.z += v.z; acc.w += v.w;
    }

    const float Tn = (float)T;
    __shared__ float red[DIM / 2];

    float lkd_pair = 0.f;
    #pragma unroll
    for (int w = 0; w < 2; ++w) {
        const int d = 2 * j + w;
        const float Sz  = w ? acc.z : acc.x;
        const float Szz = w ? acc.w : acc.y;

        const float x1  = var_vbl[d];
        const float x2  = corr_vbl[d];
        const float mu0 = prior_mu[d];

        const float sp = (x1 > 20.0f) ? x1 : log1pf(expf(x1));
        const float pv = sp * sp;
        const float sg = 1.0f / (1.0f + expf(-x2));
        const float pc = sg * pv;
        const float s  = pv - pc;

        const float P = Sz - Tn * mu0;
        const float Q = Szz - 2.0f * mu0 * Sz + Tn * mu0 * mu0;

        const float denom = s + Tn * pc;
        const float quad  = (Q - (pc / denom) * P * P) / s;

        lkd_pair += c0 - 0.5f * ((Tn - 1.0f) * logf(s) + logf(denom) + quad);
    }
    red[j] = lkd_pair;
    __syncthreads();

    #pragma unroll
    for (int off = DIM / 4; off > 0; off >>= 1) {
        if (j < off) red[j] += red[j + off];
        __syncthreads();
    }
    if (j == 0) out[0] = red[0];
}

// ---------------------------------------------------------------------------
extern "C" void kernel_launch(void* const* d_in, const int* in_sizes, int n_in,
                              void* d_out, int out_size) {
    const float* z_rest   = (const float*)d_in[0];   // [T, 512]
    const float* var_vbl  = (const float*)d_in[1];   // [512]
    const float* corr_vbl = (const float*)d_in[2];   // [512]
    const float* prior_mu = (const float*)d_in[3];   // [512]
    float* out = (float*)d_out;

    const int T = in_sizes[0] / DIM;                 // 65536
    const int rows_per_blk = T / NBLK;               // 128

    // Big constant term computed once in host double precision.
    const double LOG_2PI = 1.8378770664093454835606594728112;
    const float c0 = (float)(-0.5 * (double)T * LOG_2PI);

    dim3 blk1(THREADS_X, THREADS_Y);
    k1_reduce<<<NBLK, blk1>>>(z_rest, rows_per_blk);
    k2a_reduce<<<NB2A, DIM / 2>>>();
    k2b_final<<<1, DIM / 2>>>(var_vbl, corr_vbl, prior_mu, out, T, c0);
}